// round 15
// baseline (speedup 1.0000x reference)
#include <cuda_runtime.h>
#include <cuda_fp16.h>
#include <cstdint>

#define DINL __device__ __forceinline__

// ---------------------------------------------------------------------------
// Prepacked fp16 A-operand fragment images (uint4 = one lane's 16B of an
// m16n8k16 A-fragment).
// g_w1h: GEMM1 A = W_eff^T [256n x 800k]: [kt(25)][ks(2)][nb(16)][lane(32)]
// g_w2h: GEMM2 A = w2^T    [128n x 256k]: [ks(16)][nb(8)][lane(32)]
// g_w3h: GEMM3 A = w3^T pad [16n x 128k]: [ks(8)][lane(32)]
// ---------------------------------------------------------------------------
__device__ uint4 g_w1h[25 * 1024];
__device__ uint4 g_w2h[4096];
__device__ uint4 g_w3h[256];

DINL uint32_t h2pk(float lo, float hi) {
    uint32_t r;
    asm("cvt.rn.f16x2.f32 %0, %1, %2;" : "=r"(r) : "f"(hi), "f"(lo));
    return r;
}

DINL void mma16(float* c, const uint32_t* a, uint32_t b0, uint32_t b1) {
    asm volatile(
        "mma.sync.aligned.m16n8k16.row.col.f32.f16.f16.f32 "
        "{%0,%1,%2,%3}, {%4,%5,%6,%7}, {%8,%9}, {%0,%1,%2,%3};"
        : "+f"(c[0]), "+f"(c[1]), "+f"(c[2]), "+f"(c[3])
        : "r"(a[0]), "r"(a[1]), "r"(a[2]), "r"(a[3]), "r"(b0), "r"(b1));
}

DINL void ldm4(uint32_t* r, uint32_t addr) {
    asm volatile("ldmatrix.sync.aligned.m8n8.x4.shared.b16 {%0,%1,%2,%3}, [%4];"
                 : "=r"(r[0]), "=r"(r[1]), "=r"(r[2]), "=r"(r[3]) : "r"(addr));
}
DINL void ldm4t(uint32_t* r, uint32_t addr) {
    asm volatile("ldmatrix.sync.aligned.m8n8.x4.trans.shared.b16 {%0,%1,%2,%3}, [%4];"
                 : "=r"(r[0]), "=r"(r[1]), "=r"(r[2]), "=r"(r[3]) : "r"(addr));
}
DINL void ldm2t(uint32_t* r, uint32_t addr) {
    asm volatile("ldmatrix.sync.aligned.m8n8.x2.trans.shared.b16 {%0,%1}, [%2];"
                 : "=r"(r[0]), "=r"(r[1]) : "r"(addr));
}
DINL void lds128(uint32_t* r, uint32_t addr) {
    asm volatile("ld.shared.v4.b32 {%0,%1,%2,%3}, [%4];"
                 : "=r"(r[0]), "=r"(r[1]), "=r"(r[2]), "=r"(r[3]) : "r"(addr));
}
DINL void sts32(uint32_t addr, uint32_t v) {
    asm volatile("st.shared.b32 [%0], %1;" :: "r"(addr), "r"(v));
}
DINL void sts128(uint32_t addr, uint32_t a, uint32_t b, uint32_t c, uint32_t d) {
    asm volatile("st.shared.v4.b32 [%0], {%1,%2,%3,%4};"
                 :: "r"(addr), "r"(a), "r"(b), "r"(c), "r"(d));
}
DINL void cpa16(uint32_t dst, const void* src) {
    asm volatile("cp.async.cg.shared.global [%0], [%1], 16;" :: "r"(dst), "l"(src));
}

// ---------------------------------------------------------------------------
// Prep (v1 — best measured gap): fold conv into fc1; pack fp16 frag images.
// ---------------------------------------------------------------------------
DINL float weff(int k, int n, const float* cw, const float* w1) {
    if (k >= 784 || k < 0) return 0.f;
    int r = k / 28, c = k % 28;
    float acc = 0.f;
#pragma unroll
    for (int dr = 0; dr < 3; dr++)
#pragma unroll
        for (int dc = 0; dc < 3; dc++) {
            int rr = r - dr, cc = c - dc;
            if (rr >= 0 && rr < 26 && cc >= 0 && cc < 26)
                acc += cw[dr * 3 + dc] * w1[(rr * 26 + cc) * 256 + n];
        }
    return acc;
}

__global__ __launch_bounds__(256) void prep_kernel(
    const float* __restrict__ cw, const float* __restrict__ w1,
    const float* __restrict__ w2, const float* __restrict__ w3) {
    int gid = blockIdx.x * 256 + threadIdx.x;
    if (blockIdx.x < 100) {                       // 25600 units -> g_w1h
        int u = gid;
        int t = u & 3, g = (u >> 2) & 7, nb = (u >> 5) & 15, ks = (u >> 9) & 1, kt = u >> 10;
        int n = nb * 16 + g, k = kt * 32 + ks * 16 + 2 * t;
        uint4 v;
        v.x = h2pk(weff(k, n, cw, w1),         weff(k + 1, n, cw, w1));
        v.y = h2pk(weff(k, n + 8, cw, w1),     weff(k + 1, n + 8, cw, w1));
        v.z = h2pk(weff(k + 8, n, cw, w1),     weff(k + 9, n, cw, w1));
        v.w = h2pk(weff(k + 8, n + 8, cw, w1), weff(k + 9, n + 8, cw, w1));
        g_w1h[u] = v;
    } else if (blockIdx.x < 116) {                // 4096 units -> g_w2h
        int u = gid - 100 * 256;
        int t = u & 3, g = (u >> 2) & 7, nb = (u >> 5) & 7, ks = u >> 8;
        int n = nb * 16 + g, k = ks * 16 + 2 * t;
        uint4 v;
        v.x = h2pk(w2[k * 128 + n],           w2[(k + 1) * 128 + n]);
        v.y = h2pk(w2[k * 128 + n + 8],       w2[(k + 1) * 128 + n + 8]);
        v.z = h2pk(w2[(k + 8) * 128 + n],     w2[(k + 9) * 128 + n]);
        v.w = h2pk(w2[(k + 8) * 128 + n + 8], w2[(k + 9) * 128 + n + 8]);
        g_w2h[u] = v;
    } else {                                      // 256 units -> g_w3h
        int u = gid - 116 * 256;
        if (u < 256) {
            int t = u & 3, g = (u >> 2) & 7, ks = u >> 5;
            int k = ks * 16 + 2 * t;
            bool hi = (g + 8) < 10;
            uint4 v;
            v.x = h2pk(w3[k * 10 + g], w3[(k + 1) * 10 + g]);
            v.y = hi ? h2pk(w3[k * 10 + g + 8], w3[(k + 1) * 10 + g + 8]) : 0u;
            v.z = h2pk(w3[(k + 8) * 10 + g], w3[(k + 9) * 10 + g]);
            v.w = hi ? h2pk(w3[(k + 8) * 10 + g + 8], w3[(k + 9) * 10 + g + 8]) : 0u;
            g_w3h[u] = v;
        }
    }
}

// ---------------------------------------------------------------------------
// Fused main kernel. 256 threads = 8 warps (4 wm x 2 wn), 64 batch rows/CTA,
// 2 CTAs/SM, 128 regs/thread. GEMM1 warp tile 64n x 32b (acc 64 f32);
// 25 k-tiles of 32, 4-stage cp.async ring.
// ---------------------------------------------------------------------------
constexpr int XP   = 80;                           // x row pitch bytes
constexpr int XSTG = 64 * XP;                      // 5120
constexpr int WSTG = 16384;
constexpr int STG  = XSTG + WSTG;                  // 21504; ring = 4*STG = 86016
constexpr int HP   = 144;                          // h row pitch bytes
constexpr int OFF_H1 = 0;                          // [256 rows][144B] (aliases ring)
constexpr int OFF_H2 = 36864;                      // [128 rows][144B] -> 55296
constexpr int OFF_B1 = 86016;                      // beyond ring
constexpr int OFF_B2 = 87040;
constexpr int OFF_B3 = 87552;
constexpr int SMEMB  = 87616;

__global__ __launch_bounds__(256, 2) void fused_kernel(
    const float* __restrict__ x, const float* __restrict__ b1,
    const float* __restrict__ b2, const float* __restrict__ b3,
    float* __restrict__ out) {
    extern __shared__ char sm[];
    const uint32_t smb = (uint32_t)__cvta_generic_to_shared(sm);
    const int tid = threadIdx.x, w = tid >> 5, lane = tid & 31;
    const int g = lane >> 2, q = lane & 3;
    const int wm = w >> 1, wn = w & 1;              // wm 0..3, wn 0..1
    const int m0 = blockIdx.x * 64;
    float* B1f = (float*)(sm + OFF_B1);
    float* B2f = (float*)(sm + OFF_B2);
    float* B3f = (float*)(sm + OFF_B3);

    B1f[tid] = b1[tid];
    if (tid < 128) B2f[tid] = b2[tid];
    if (tid < 16)  B3f[tid] = (tid < 10) ? b3[tid] : 0.f;

    // x path: thread owns row = tid>>2, 8 float cols at (tid&3)*8
    const int xr = tid >> 2, xc = (tid & 3) * 8;
    const float* xrow = x + (size_t)(m0 + xr) * 784;
    uint32_t xp0, xp1, xp2, xp3;

    auto ldgx = [&](int t) {
        int col = t * 32 + xc;
        float4 f0 = make_float4(0.f, 0.f, 0.f, 0.f);
        float4 f1 = make_float4(0.f, 0.f, 0.f, 0.f);
        if (col < 784) {
            f0 = *(const float4*)(xrow + col);
            f1 = *(const float4*)(xrow + col + 4);
        }
        xp0 = h2pk(f0.x, f0.y); xp1 = h2pk(f0.z, f0.w);
        xp2 = h2pk(f1.x, f1.y); xp3 = h2pk(f1.z, f1.w);
    };
    const uint32_t xsd = smb + (uint32_t)(xr * XP + xc * 2);
    auto stsx = [&](int t) {
        sts128(xsd + (uint32_t)((t & 3) * STG), xp0, xp1, xp2, xp3);
    };
    const uint32_t wsd = smb + XSTG + (uint32_t)tid * 16;
    auto issueW = [&](int t) {           // exactly 16KB = 1024 x 16B
        uint32_t d = wsd + (uint32_t)((t & 3) * STG);
        const uint4* src = g_w1h + t * 1024 + tid;
        cpa16(d,            src);
        cpa16(d + 256 * 16, src + 256);
        cpa16(d + 512 * 16, src + 512);
        cpa16(d + 768 * 16, src + 768);
        asm volatile("cp.async.commit_group;");
    };

    // prologue
    ldgx(0); stsx(0); issueW(0);
    ldgx(1); stsx(1); issueW(1);
    ldgx(2); stsx(2); issueW(2);
    ldgx(3);

    // per-warp frag base addresses (stage-relative)
    const uint32_t aBase = smb + XSTG + (uint32_t)(((wm * 4) * 32 + lane) * 16);
    const uint32_t bBase = smb
        + (uint32_t)((wn * 32 + (lane & 7) + ((lane >> 4) & 1) * 8) * XP
                     + ((lane >> 3) & 1) * 16);

    // ---------------- GEMM1: [256n] x [800k] x [64b], warp 64n x 32b -------
    float acc[4][4][4];
#pragma unroll
    for (int a = 0; a < 4; a++)
#pragma unroll
        for (int b = 0; b < 4; b++)
#pragma unroll
            for (int c = 0; c < 4; c++) acc[a][b][c] = 0.f;

    for (int t = 0; t < 25; t++) {
        if (t <= 22)      asm volatile("cp.async.wait_group 2;");
        else if (t == 23) asm volatile("cp.async.wait_group 1;");
        else              asm volatile("cp.async.wait_group 0;");
        __syncthreads();
        if (t + 3 < 25) { stsx(t + 3); issueW(t + 3); }
        if (t + 4 < 25) ldgx(t + 4);

        const uint32_t xs = smb + (uint32_t)((t & 3) * STG);
        const uint32_t aS = aBase + xs - smb;      // = aBase + stage offset
        const uint32_t bS = bBase + xs - smb;
#pragma unroll
        for (int ks = 0; ks < 2; ks++) {
            uint32_t B0[4], B1r[4];
            ldm4(B0,  bS + (uint32_t)(ks * 32));
            ldm4(B1r, bS + (uint32_t)(16 * XP + ks * 32));
#pragma unroll
            for (int mf = 0; mf < 4; mf++) {
                uint32_t A[4];
                lds128(A, aS + (uint32_t)(((ks * 16 + mf) * 32) * 16));
                mma16(acc[mf][0], A, B0[0],  B0[1]);
                mma16(acc[mf][1], A, B0[2],  B0[3]);
                mma16(acc[mf][2], A, B1r[0], B1r[1]);
                mma16(acc[mf][3], A, B1r[2], B1r[3]);
            }
        }
    }
    __syncthreads();   // ring consumed; safe to overwrite with h1

    // epilogue 1: relu(acc+b1) -> h1 fp16 [n1 rows, 144B pitch][64b]
#pragma unroll
    for (int mf = 0; mf < 4; mf++) {
        int n = wm * 64 + mf * 16 + g;
        float bi0 = B1f[n], bi8 = B1f[n + 8];
#pragma unroll
        for (int nf = 0; nf < 4; nf++) {
            int bc = wn * 32 + nf * 8 + 2 * q;
            float* a = acc[mf][nf];
            sts32(smb + (uint32_t)(OFF_H1 + n * HP + bc * 2),
                  h2pk(fmaxf(a[0] + bi0, 0.f), fmaxf(a[1] + bi0, 0.f)));
            sts32(smb + (uint32_t)(OFF_H1 + (n + 8) * HP + bc * 2),
                  h2pk(fmaxf(a[2] + bi8, 0.f), fmaxf(a[3] + bi8, 0.f)));
        }
    }
    __syncthreads();

    // ---------------- GEMM2: [128n2] x [256k] x [64b], warp 32n x 32b -------
    float a2[2][4][4];
#pragma unroll
    for (int a = 0; a < 2; a++)
#pragma unroll
        for (int b = 0; b < 4; b++)
#pragma unroll
            for (int c = 0; c < 4; c++) a2[a][b][c] = 0.f;

    uint4 an0 = g_w2h[(wm * 2) * 32 + lane];
    uint4 an1 = g_w2h[(wm * 2 + 1) * 32 + lane];
#pragma unroll 4
    for (int ks = 0; ks < 16; ks++) {
        uint32_t A0[4] = {an0.x, an0.y, an0.z, an0.w};
        uint32_t A1[4] = {an1.x, an1.y, an1.z, an1.w};
        if (ks < 15) {
            an0 = g_w2h[((ks + 1) * 8 + wm * 2) * 32 + lane];
            an1 = g_w2h[((ks + 1) * 8 + wm * 2 + 1) * 32 + lane];
        }
#pragma unroll
        for (int nfp = 0; nfp < 2; nfp++) {
            uint32_t B[4];
            uint32_t badr = smb
                + (uint32_t)(OFF_H1 + (ks * 16 + (lane & 7) + ((lane >> 3) & 1) * 8) * HP
                             + (wn * 32 + nfp * 16 + ((lane >> 4) & 1) * 8) * 2);
            ldm4t(B, badr);
            mma16(a2[0][nfp * 2],     A0, B[0], B[1]);
            mma16(a2[0][nfp * 2 + 1], A0, B[2], B[3]);
            mma16(a2[1][nfp * 2],     A1, B[0], B[1]);
            mma16(a2[1][nfp * 2 + 1], A1, B[2], B[3]);
        }
    }

    // epilogue 2: relu(a2+b2) -> h2 fp16 [n2 rows][64b]
#pragma unroll
    for (int mf = 0; mf < 2; mf++) {
        int n = wm * 32 + mf * 16 + g;
        float bi0 = B2f[n], bi8 = B2f[n + 8];
#pragma unroll
        for (int nf = 0; nf < 4; nf++) {
            int bc = wn * 32 + nf * 8 + 2 * q;
            float* a = a2[mf][nf];
            sts32(smb + (uint32_t)(OFF_H2 + n * HP + bc * 2),
                  h2pk(fmaxf(a[0] + bi0, 0.f), fmaxf(a[1] + bi0, 0.f)));
            sts32(smb + (uint32_t)(OFF_H2 + (n + 8) * HP + bc * 2),
                  h2pk(fmaxf(a[2] + bi8, 0.f), fmaxf(a[3] + bi8, 0.f)));
        }
    }
    __syncthreads();

    // ---------------- GEMM3: [16n3] x [128k] x [64b], 8 warps x 8b ----------
    {
        float a3[4] = {0.f, 0.f, 0.f, 0.f};
        uint4 a3nx = g_w3h[lane];
#pragma unroll
        for (int ks = 0; ks < 8; ks++) {
            uint32_t A[4];
            A[0] = a3nx.x; A[1] = a3nx.y; A[2] = a3nx.z; A[3] = a3nx.w;
            if (ks < 7) a3nx = g_w3h[(ks + 1) * 32 + lane];
            uint32_t B[2];
            int l = lane & 15;
            uint32_t badr = smb
                + (uint32_t)(OFF_H2 + (ks * 16 + (l & 7) + ((l >> 3) & 1) * 8) * HP + w * 16);
            ldm2t(B, badr);
            mma16(a3, A, B[0], B[1]);
        }
        int b = m0 + w * 8 + 2 * q;
        out[(size_t)b * 10 + g]       = a3[0] + B3f[g];
        out[(size_t)(b + 1) * 10 + g] = a3[1] + B3f[g];
        if (g < 2) {
            out[(size_t)b * 10 + g + 8]       = a3[2] + B3f[g + 8];
            out[(size_t)(b + 1) * 10 + g + 8] = a3[3] + B3f[g + 8];
        }
    }
}

// ---------------------------------------------------------------------------
extern "C" void kernel_launch(void* const* d_in, const int* in_sizes, int n_in,
                              void* d_out, int out_size) {
    const float* x    = (const float*)d_in[0];
    const float* conv = (const float*)d_in[1];
    const float* w1   = (const float*)d_in[2];
    const float* b1   = (const float*)d_in[3];
    const float* w2   = (const float*)d_in[4];
    const float* b2   = (const float*)d_in[5];
    const float* w3   = (const float*)d_in[6];
    const float* b3   = (const float*)d_in[7];
    float* out = (float*)d_out;

    prep_kernel<<<117, 256>>>(conv, w1, w2, w3);

    cudaFuncSetAttribute(fused_kernel, cudaFuncAttributeMaxDynamicSharedMemorySize, SMEMB);
    fused_kernel<<<1024, 256, SMEMB>>>(x, b1, b2, b3, out);
}

// round 16
// speedup vs baseline: 1.0467x; 1.0467x over previous
#include <cuda_runtime.h>
#include <cuda_fp16.h>
#include <cstdint>

#define DINL __device__ __forceinline__

// ---------------------------------------------------------------------------
// Prepacked fp16 A-operand fragment images (uint4 = one lane's 16B of an
// m16n8k16 A-fragment).
// g_w1h: GEMM1 A = W_eff^T [256n x 800k]: [kt(25)][ks(2)][nb(16)][lane(32)]
// g_w2h: GEMM2 A = w2^T    [128n x 256k]: [ks(16)][nb(8)][lane(32)]
// g_w3h: GEMM3 A = w3^T pad [16n x 128k]: [ks(8)][lane(32)]
// ---------------------------------------------------------------------------
__device__ uint4 g_w1h[25 * 1024];
__device__ uint4 g_w2h[4096];
__device__ uint4 g_w3h[256];

DINL uint32_t h2pk(float lo, float hi) {
    uint32_t r;
    asm("cvt.rn.f16x2.f32 %0, %1, %2;" : "=r"(r) : "f"(hi), "f"(lo));
    return r;
}

DINL void mma16(float* c, const uint32_t* a, uint32_t b0, uint32_t b1) {
    asm volatile(
        "mma.sync.aligned.m16n8k16.row.col.f32.f16.f16.f32 "
        "{%0,%1,%2,%3}, {%4,%5,%6,%7}, {%8,%9}, {%0,%1,%2,%3};"
        : "+f"(c[0]), "+f"(c[1]), "+f"(c[2]), "+f"(c[3])
        : "r"(a[0]), "r"(a[1]), "r"(a[2]), "r"(a[3]), "r"(b0), "r"(b1));
}

DINL void ldm4(uint32_t* r, uint32_t addr) {
    asm volatile("ldmatrix.sync.aligned.m8n8.x4.shared.b16 {%0,%1,%2,%3}, [%4];"
                 : "=r"(r[0]), "=r"(r[1]), "=r"(r[2]), "=r"(r[3]) : "r"(addr));
}
DINL void ldm4t(uint32_t* r, uint32_t addr) {
    asm volatile("ldmatrix.sync.aligned.m8n8.x4.trans.shared.b16 {%0,%1,%2,%3}, [%4];"
                 : "=r"(r[0]), "=r"(r[1]), "=r"(r[2]), "=r"(r[3]) : "r"(addr));
}
DINL void ldm2t(uint32_t* r, uint32_t addr) {
    asm volatile("ldmatrix.sync.aligned.m8n8.x2.trans.shared.b16 {%0,%1}, [%2];"
                 : "=r"(r[0]), "=r"(r[1]) : "r"(addr));
}
DINL void sts32(uint32_t addr, uint32_t v) {
    asm volatile("st.shared.b32 [%0], %1;" :: "r"(addr), "r"(v));
}
DINL void sts64(uint32_t addr, uint32_t v0, uint32_t v1) {
    asm volatile("st.shared.v2.b32 [%0], {%1,%2};" :: "r"(addr), "r"(v0), "r"(v1));
}

// ---------------------------------------------------------------------------
// Prep (v1 — best measured gap): fold conv into fc1; pack fp16 frag images.
// ---------------------------------------------------------------------------
DINL float weff(int k, int n, const float* cw, const float* w1) {
    if (k >= 784 || k < 0) return 0.f;
    int r = k / 28, c = k % 28;
    float acc = 0.f;
#pragma unroll
    for (int dr = 0; dr < 3; dr++)
#pragma unroll
        for (int dc = 0; dc < 3; dc++) {
            int rr = r - dr, cc = c - dc;
            if (rr >= 0 && rr < 26 && cc >= 0 && cc < 26)
                acc += cw[dr * 3 + dc] * w1[(rr * 26 + cc) * 256 + n];
        }
    return acc;
}

__global__ __launch_bounds__(256) void prep_kernel(
    const float* __restrict__ cw, const float* __restrict__ w1,
    const float* __restrict__ w2, const float* __restrict__ w3) {
    int gid = blockIdx.x * 256 + threadIdx.x;
    if (blockIdx.x < 100) {                       // 25600 units -> g_w1h
        int u = gid;
        int t = u & 3, g = (u >> 2) & 7, nb = (u >> 5) & 15, ks = (u >> 9) & 1, kt = u >> 10;
        int n = nb * 16 + g, k = kt * 32 + ks * 16 + 2 * t;
        uint4 v;
        v.x = h2pk(weff(k, n, cw, w1),         weff(k + 1, n, cw, w1));
        v.y = h2pk(weff(k, n + 8, cw, w1),     weff(k + 1, n + 8, cw, w1));
        v.z = h2pk(weff(k + 8, n, cw, w1),     weff(k + 9, n, cw, w1));
        v.w = h2pk(weff(k + 8, n + 8, cw, w1), weff(k + 9, n + 8, cw, w1));
        g_w1h[u] = v;
    } else if (blockIdx.x < 116) {                // 4096 units -> g_w2h
        int u = gid - 100 * 256;
        int t = u & 3, g = (u >> 2) & 7, nb = (u >> 5) & 7, ks = u >> 8;
        int n = nb * 16 + g, k = ks * 16 + 2 * t;
        uint4 v;
        v.x = h2pk(w2[k * 128 + n],           w2[(k + 1) * 128 + n]);
        v.y = h2pk(w2[k * 128 + n + 8],       w2[(k + 1) * 128 + n + 8]);
        v.z = h2pk(w2[(k + 8) * 128 + n],     w2[(k + 9) * 128 + n]);
        v.w = h2pk(w2[(k + 8) * 128 + n + 8], w2[(k + 9) * 128 + n + 8]);
        g_w2h[u] = v;
    } else {                                      // 256 units -> g_w3h
        int u = gid - 116 * 256;
        if (u < 256) {
            int t = u & 3, g = (u >> 2) & 7, ks = u >> 5;
            int k = ks * 16 + 2 * t;
            bool hi = (g + 8) < 10;
            uint4 v;
            v.x = h2pk(w3[k * 10 + g], w3[(k + 1) * 10 + g]);
            v.y = hi ? h2pk(w3[k * 10 + g + 8], w3[(k + 1) * 10 + g + 8]) : 0u;
            v.z = h2pk(w3[(k + 8) * 10 + g], w3[(k + 9) * 10 + g]);
            v.w = hi ? h2pk(w3[(k + 8) * 10 + g + 8], w3[(k + 9) * 10 + g + 8]) : 0u;
            g_w3h[u] = v;
        }
    }
}

// ---------------------------------------------------------------------------
// Fused main kernel. 512 threads = 16 warps (8 wm x 2 wn), 64 batch rows/CTA,
// 2 CTAs/SM. GEMM1 warp tile 32n x 32b; 25 k-tiles of 32. GEMM1 A-frags are
// LDG'd directly from the L2-resident g_w1h image (one ks-step prefetch in
// regs); only the x tile is staged in smem (4-stage STS ring, 1 sync/tile).
// ---------------------------------------------------------------------------
constexpr int XP   = 80;                           // x row pitch bytes
constexpr int XSTG = 64 * XP;                      // 5120; ring = 4*XSTG = 20480
constexpr int HP   = 144;                          // h row pitch bytes
constexpr int OFF_H1 = 0;                          // [256 rows][144B] (aliases ring)
constexpr int OFF_H2 = 36864;                      // [128 rows][144B] -> 55296
constexpr int OFF_B1 = 55296;
constexpr int OFF_B2 = 56320;
constexpr int OFF_B3 = 56832;
constexpr int SMEMB  = 56896;                      // 2 CTAs/SM trivially fits

__global__ __launch_bounds__(512, 2) void fused_kernel(
    const float* __restrict__ x, const float* __restrict__ b1,
    const float* __restrict__ b2, const float* __restrict__ b3,
    float* __restrict__ out) {
    extern __shared__ char sm[];
    const uint32_t smb = (uint32_t)__cvta_generic_to_shared(sm);
    const int tid = threadIdx.x, w = tid >> 5, lane = tid & 31;
    const int g = lane >> 2, q = lane & 3;
    const int wm = w >> 1, wn = w & 1;
    const int m0 = blockIdx.x * 64;
    float* B1f = (float*)(sm + OFF_B1);
    float* B2f = (float*)(sm + OFF_B2);
    float* B3f = (float*)(sm + OFF_B3);

    if (tid < 256) B1f[tid] = b1[tid];
    if (tid < 128) B2f[tid] = b2[tid];
    if (tid < 16)  B3f[tid] = (tid < 10) ? b3[tid] : 0.f;

    // x path: thread owns row = tid>>3, 4 float cols at (tid&7)*4
    const int xr = tid >> 3, xc = (tid & 7) * 4;
    const float* xrow = x + (size_t)(m0 + xr) * 784;
    float4 fb;

    auto ldgx = [&](int t) {
        int col = t * 32 + xc;
        if (col < 784) fb = *(const float4*)(xrow + col);
        else           fb = make_float4(0.f, 0.f, 0.f, 0.f);
    };
    const uint32_t xsd = smb + (uint32_t)(xr * XP + xc * 2);
    auto stsx = [&](int t) {
        sts64(xsd + (uint32_t)((t & 3) * XSTG), h2pk(fb.x, fb.y), h2pk(fb.z, fb.w));
    };

    // prologue: x tiles 0..2 staged, tile 3 in regs
    ldgx(0); stsx(0);
    ldgx(1); stsx(1);
    ldgx(2); stsx(2);
    ldgx(3);

    // per-warp bases
    const uint32_t bBase = smb
        + (uint32_t)((wn * 32 + (lane & 7) + ((lane >> 4) & 1) * 8) * XP
                     + ((lane >> 3) & 1) * 16);
    const uint4* aPtr = g_w1h + (wm * 2) * 32 + lane;   // mf0; mf1 at +32

    // ---------------- GEMM1: [256n] x [800k] x [64b] ----------------
    float acc[2][4][4];
#pragma unroll
    for (int a = 0; a < 2; a++)
#pragma unroll
        for (int b = 0; b < 4; b++)
#pragma unroll
            for (int c = 0; c < 4; c++) acc[a][b][c] = 0.f;

    uint4 aN0 = aPtr[0];        // A-frags for k-step 0, mf0/mf1
    uint4 aN1 = aPtr[32];

    for (int t = 0; t < 25; t++) {
        __syncthreads();                       // stage (t-1)&3 free; tile t visible
        if (t + 3 < 25) stsx(t + 3);
        if (t + 4 < 25) ldgx(t + 4);

        const uint32_t bS = bBase + (uint32_t)((t & 3) * XSTG);
#pragma unroll
        for (int ks = 0; ks < 2; ks++) {
            uint32_t A0[4] = {aN0.x, aN0.y, aN0.z, aN0.w};
            uint32_t A1[4] = {aN1.x, aN1.y, aN1.z, aN1.w};
            const int step = t * 2 + ks;
            if (step < 49) {                   // prefetch next k-step frags
                aN0 = aPtr[(step + 1) * 512];
                aN1 = aPtr[(step + 1) * 512 + 32];
            }
#pragma unroll
            for (int nfp = 0; nfp < 2; nfp++) {
                uint32_t B[4];
                ldm4(B, bS + (uint32_t)(nfp * 16 * XP + ks * 32));
                mma16(acc[0][nfp * 2],     A0, B[0], B[1]);
                mma16(acc[0][nfp * 2 + 1], A0, B[2], B[3]);
                mma16(acc[1][nfp * 2],     A1, B[0], B[1]);
                mma16(acc[1][nfp * 2 + 1], A1, B[2], B[3]);
            }
        }
    }
    __syncthreads();   // ring consumed; safe to overwrite with h1

    // epilogue 1: relu(acc+b1) -> h1 fp16 [n1 rows, 144B pitch][64b]
#pragma unroll
    for (int mf = 0; mf < 2; mf++) {
        int n = wm * 32 + mf * 16 + g;
        float bi0 = B1f[n], bi8 = B1f[n + 8];
#pragma unroll
        for (int nf = 0; nf < 4; nf++) {
            int bc = wn * 32 + nf * 8 + 2 * q;
            float* a = acc[mf][nf];
            sts32(smb + (uint32_t)(OFF_H1 + n * HP + bc * 2),
                  h2pk(fmaxf(a[0] + bi0, 0.f), fmaxf(a[1] + bi0, 0.f)));
            sts32(smb + (uint32_t)(OFF_H1 + (n + 8) * HP + bc * 2),
                  h2pk(fmaxf(a[2] + bi8, 0.f), fmaxf(a[3] + bi8, 0.f)));
        }
    }
    __syncthreads();

    // ---------------- GEMM2: [128n2] x [256k] x [64b], A from global --------
    float a2[4][4];
#pragma unroll
    for (int b = 0; b < 4; b++)
#pragma unroll
        for (int c = 0; c < 4; c++) a2[b][c] = 0.f;

    uint4 anx = g_w2h[wm * 32 + lane];
#pragma unroll 4
    for (int ks = 0; ks < 16; ks++) {
        uint32_t A[4];
        A[0] = anx.x; A[1] = anx.y; A[2] = anx.z; A[3] = anx.w;
        if (ks < 15) anx = g_w2h[((ks + 1) * 8 + wm) * 32 + lane];
#pragma unroll
        for (int nfp = 0; nfp < 2; nfp++) {
            uint32_t B[4];
            uint32_t badr = smb
                + (uint32_t)(OFF_H1 + (ks * 16 + (lane & 7) + ((lane >> 3) & 1) * 8) * HP
                             + (wn * 32 + nfp * 16 + ((lane >> 4) & 1) * 8) * 2);
            ldm4t(B, badr);
            mma16(a2[nfp * 2],     A, B[0], B[1]);
            mma16(a2[nfp * 2 + 1], A, B[2], B[3]);
        }
    }

    // epilogue 2: relu(a2+b2) -> h2 fp16 [n2 rows][64b]
    {
        int n = wm * 16 + g;
        float bi0 = B2f[n], bi8 = B2f[n + 8];
#pragma unroll
        for (int nf = 0; nf < 4; nf++) {
            int bc = wn * 32 + nf * 8 + 2 * q;
            float* a = a2[nf];
            sts32(smb + (uint32_t)(OFF_H2 + n * HP + bc * 2),
                  h2pk(fmaxf(a[0] + bi0, 0.f), fmaxf(a[1] + bi0, 0.f)));
            sts32(smb + (uint32_t)(OFF_H2 + (n + 8) * HP + bc * 2),
                  h2pk(fmaxf(a[2] + bi8, 0.f), fmaxf(a[3] + bi8, 0.f)));
        }
    }
    __syncthreads();

    // ---------------- GEMM3: [16n3] x [128k] x [64b], 8 warps x 8b ----------
    if (w < 8) {
        float a3[4] = {0.f, 0.f, 0.f, 0.f};
        uint4 a3nx = g_w3h[lane];
#pragma unroll
        for (int ks = 0; ks < 8; ks++) {
            uint32_t A[4];
            A[0] = a3nx.x; A[1] = a3nx.y; A[2] = a3nx.z; A[3] = a3nx.w;
            if (ks < 7) a3nx = g_w3h[(ks + 1) * 32 + lane];
            uint32_t B[2];
            int l = lane & 15;
            uint32_t badr = smb
                + (uint32_t)(OFF_H2 + (ks * 16 + (l & 7) + ((l >> 3) & 1) * 8) * HP + w * 16);
            ldm2t(B, badr);
            mma16(a3, A, B[0], B[1]);
        }
        int b = m0 + w * 8 + 2 * q;
        out[(size_t)b * 10 + g]       = a3[0] + B3f[g];
        out[(size_t)(b + 1) * 10 + g] = a3[1] + B3f[g];
        if (g < 2) {
            out[(size_t)b * 10 + g + 8]       = a3[2] + B3f[g + 8];
            out[(size_t)(b + 1) * 10 + g + 8] = a3[3] + B3f[g + 8];
        }
    }
}

// ---------------------------------------------------------------------------
extern "C" void kernel_launch(void* const* d_in, const int* in_sizes, int n_in,
                              void* d_out, int out_size) {
    const float* x    = (const float*)d_in[0];
    const float* conv = (const float*)d_in[1];
    const float* w1   = (const float*)d_in[2];
    const float* b1   = (const float*)d_in[3];
    const float* w2   = (const float*)d_in[4];
    const float* b2   = (const float*)d_in[5];
    const float* w3   = (const float*)d_in[6];
    const float* b3   = (const float*)d_in[7];
    float* out = (float*)d_out;

    prep_kernel<<<117, 256>>>(conv, w1, w2, w3);

    cudaFuncSetAttribute(fused_kernel, cudaFuncAttributeMaxDynamicSharedMemorySize, SMEMB);
    fused_kernel<<<1024, 512, SMEMB>>>(x, b1, b2, b3, out);
}

// round 17
// speedup vs baseline: 1.2336x; 1.1786x over previous
#include <cuda_runtime.h>
#include <cuda_fp16.h>
#include <cstdint>

#define DINL __device__ __forceinline__

// ---------------------------------------------------------------------------
// Prepacked fp16 A-operand fragment images (uint4 = one lane's 16B of an
// m16n8k16 A-fragment).
// g_w1h: GEMM1 A = W_eff^T [256n x 800k]: [kt(25)][ks(2)][nb(16)][lane(32)]
// g_w2h: GEMM2 A = w2^T    [128n x 256k]: [ks(16)][nb(8)][lane(32)]
// g_w3h: GEMM3 A = w3^T pad [16n x 128k]: [ks(8)][lane(32)]
// ---------------------------------------------------------------------------
__device__ uint4 g_w1h[25 * 1024];
__device__ uint4 g_w2h[4096];
__device__ uint4 g_w3h[256];

DINL uint32_t h2pk(float lo, float hi) {
    uint32_t r;
    asm("cvt.rn.f16x2.f32 %0, %1, %2;" : "=r"(r) : "f"(hi), "f"(lo));
    return r;
}

DINL void mma16(float* c, const uint32_t* a, uint32_t b0, uint32_t b1) {
    asm volatile(
        "mma.sync.aligned.m16n8k16.row.col.f32.f16.f16.f32 "
        "{%0,%1,%2,%3}, {%4,%5,%6,%7}, {%8,%9}, {%0,%1,%2,%3};"
        : "+f"(c[0]), "+f"(c[1]), "+f"(c[2]), "+f"(c[3])
        : "r"(a[0]), "r"(a[1]), "r"(a[2]), "r"(a[3]), "r"(b0), "r"(b1));
}

DINL void ldm4(uint32_t* r, uint32_t addr) {
    asm volatile("ldmatrix.sync.aligned.m8n8.x4.shared.b16 {%0,%1,%2,%3}, [%4];"
                 : "=r"(r[0]), "=r"(r[1]), "=r"(r[2]), "=r"(r[3]) : "r"(addr));
}
DINL void ldm4t(uint32_t* r, uint32_t addr) {
    asm volatile("ldmatrix.sync.aligned.m8n8.x4.trans.shared.b16 {%0,%1,%2,%3}, [%4];"
                 : "=r"(r[0]), "=r"(r[1]), "=r"(r[2]), "=r"(r[3]) : "r"(addr));
}
DINL void ldm2t(uint32_t* r, uint32_t addr) {
    asm volatile("ldmatrix.sync.aligned.m8n8.x2.trans.shared.b16 {%0,%1}, [%2];"
                 : "=r"(r[0]), "=r"(r[1]) : "r"(addr));
}
DINL void lds128(uint32_t* r, uint32_t addr) {
    asm volatile("ld.shared.v4.b32 {%0,%1,%2,%3}, [%4];"
                 : "=r"(r[0]), "=r"(r[1]), "=r"(r[2]), "=r"(r[3]) : "r"(addr));
}
DINL void sts32(uint32_t addr, uint32_t v) {
    asm volatile("st.shared.b32 [%0], %1;" :: "r"(addr), "r"(v));
}
DINL void sts64(uint32_t addr, uint32_t v0, uint32_t v1) {
    asm volatile("st.shared.v2.b32 [%0], {%1,%2};" :: "r"(addr), "r"(v0), "r"(v1));
}
DINL void cpa16(uint32_t dst, const void* src) {
    asm volatile("cp.async.cg.shared.global [%0], [%1], 16;" :: "r"(dst), "l"(src));
}

// ---------------------------------------------------------------------------
// Prep v4: same math/order as v1, 4x finer thread decomposition (one thread
// per packed uint32 component -> 4x the threads, 4x shorter LDG chains).
// Blocks 0..399: g_w1h components. 400..415: g_w2h. 416: g_w3h.
// ---------------------------------------------------------------------------
DINL float weff(int k, int n, const float* cw, const float* w1) {
    if (k >= 784 || k < 0) return 0.f;
    int r = k / 28, c = k % 28;
    float acc = 0.f;
#pragma unroll
    for (int dr = 0; dr < 3; dr++)
#pragma unroll
        for (int dc = 0; dc < 3; dc++) {
            int rr = r - dr, cc = c - dc;
            if (rr >= 0 && rr < 26 && cc >= 0 && cc < 26)
                acc += cw[dr * 3 + dc] * w1[(rr * 26 + cc) * 256 + n];
        }
    return acc;
}

__global__ __launch_bounds__(256) void prep_kernel(
    const float* __restrict__ cw, const float* __restrict__ w1,
    const float* __restrict__ w2, const float* __restrict__ w3) {
    int gid = blockIdx.x * 256 + threadIdx.x;
    if (blockIdx.x < 400) {                       // 102400 components -> g_w1h
        int comp = gid & 3, u = gid >> 2;
        int t = u & 3, g = (u >> 2) & 7, nb = (u >> 5) & 15, ks = (u >> 9) & 1, kt = u >> 10;
        int n = nb * 16 + g + ((comp & 1) ? 8 : 0);
        int k = kt * 32 + ks * 16 + 2 * t + ((comp >= 2) ? 8 : 0);
        ((uint32_t*)&g_w1h[u])[comp] = h2pk(weff(k, n, cw, w1), weff(k + 1, n, cw, w1));
    } else if (blockIdx.x < 416) {                // 4096 units -> g_w2h
        int u = gid - 400 * 256;
        int t = u & 3, g = (u >> 2) & 7, nb = (u >> 5) & 7, ks = u >> 8;
        int n = nb * 16 + g, k = ks * 16 + 2 * t;
        uint4 v;
        v.x = h2pk(w2[k * 128 + n],           w2[(k + 1) * 128 + n]);
        v.y = h2pk(w2[k * 128 + n + 8],       w2[(k + 1) * 128 + n + 8]);
        v.z = h2pk(w2[(k + 8) * 128 + n],     w2[(k + 9) * 128 + n]);
        v.w = h2pk(w2[(k + 8) * 128 + n + 8], w2[(k + 9) * 128 + n + 8]);
        g_w2h[u] = v;
    } else {                                      // 256 units -> g_w3h
        int u = gid - 416 * 256;
        if (u < 256) {
            int t = u & 3, g = (u >> 2) & 7, ks = u >> 5;
            int k = ks * 16 + 2 * t;
            bool hi = (g + 8) < 10;
            uint4 v;
            v.x = h2pk(w3[k * 10 + g], w3[(k + 1) * 10 + g]);
            v.y = hi ? h2pk(w3[k * 10 + g + 8], w3[(k + 1) * 10 + g + 8]) : 0u;
            v.z = h2pk(w3[(k + 8) * 10 + g], w3[(k + 9) * 10 + g]);
            v.w = hi ? h2pk(w3[(k + 8) * 10 + g + 8], w3[(k + 9) * 10 + g + 8]) : 0u;
            g_w3h[u] = v;
        }
    }
}

// ---------------------------------------------------------------------------
// Fused main kernel (R9 verbatim — proven 110.4-111.5 us). 512 threads =
// 16 warps (8 wm x 2 wn), 64 batch rows/CTA, 2 CTAs/SM. GEMM1 warp tile
// 32n x 32b; 25 k-tiles of 32, 4-stage cp.async ring.
// ---------------------------------------------------------------------------
constexpr int XP   = 80;                           // x row pitch bytes
constexpr int XSTG = 64 * XP;                      // 5120
constexpr int WSTG = 16384;
constexpr int STG  = XSTG + WSTG;                  // 21504; ring = 4*STG = 86016
constexpr int HP   = 144;                          // h row pitch bytes
constexpr int OFF_H1 = 0;                          // [256 rows][144B] (aliases ring)
constexpr int OFF_H2 = 36864;                      // [128 rows][144B] -> 55296
constexpr int OFF_B1 = 86016;                      // beyond ring
constexpr int OFF_B2 = 87040;
constexpr int OFF_B3 = 87552;
constexpr int SMEMB  = 87616;

__global__ __launch_bounds__(512, 2) void fused_kernel(
    const float* __restrict__ x, const float* __restrict__ b1,
    const float* __restrict__ b2, const float* __restrict__ b3,
    float* __restrict__ out) {
    extern __shared__ char sm[];
    const uint32_t smb = (uint32_t)__cvta_generic_to_shared(sm);
    const int tid = threadIdx.x, w = tid >> 5, lane = tid & 31;
    const int g = lane >> 2, q = lane & 3;
    const int wm = w >> 1, wn = w & 1;
    const int m0 = blockIdx.x * 64;
    float* B1f = (float*)(sm + OFF_B1);
    float* B2f = (float*)(sm + OFF_B2);
    float* B3f = (float*)(sm + OFF_B3);

    if (tid < 256) B1f[tid] = b1[tid];
    if (tid < 128) B2f[tid] = b2[tid];
    if (tid < 16)  B3f[tid] = (tid < 10) ? b3[tid] : 0.f;

    // x path: thread owns row = tid>>3, 4 float cols at (tid&7)*4
    const int xr = tid >> 3, xc = (tid & 7) * 4;
    const float* xrow = x + (size_t)(m0 + xr) * 784;
    float4 fb;

    auto ldgx = [&](int t) {
        int col = t * 32 + xc;
        if (col < 784) fb = *(const float4*)(xrow + col);
        else           fb = make_float4(0.f, 0.f, 0.f, 0.f);
    };
    auto stsx = [&](int t) {
        uint32_t d = smb + (uint32_t)((t & 3) * STG + xr * XP + xc * 2);
        sts64(d, h2pk(fb.x, fb.y), h2pk(fb.z, fb.w));
    };
    auto issueW = [&](int t) {           // exactly 16KB = 1024 x 16B
        uint32_t d = smb + (uint32_t)((t & 3) * STG + XSTG);
        const uint4* src = g_w1h + t * 1024;
#pragma unroll
        for (int i = 0; i < 2; i++) {
            int idx = tid + i * 512;
            cpa16(d + idx * 16, src + idx);
        }
        asm volatile("cp.async.commit_group;");
    };

    // prologue
    ldgx(0); stsx(0); issueW(0);
    ldgx(1); stsx(1); issueW(1);
    ldgx(2); stsx(2); issueW(2);
    ldgx(3);

    // ---------------- GEMM1: [256n] x [800k] x [64b] ----------------
    float acc[2][4][4];
#pragma unroll
    for (int a = 0; a < 2; a++)
#pragma unroll
        for (int b = 0; b < 4; b++)
#pragma unroll
            for (int c = 0; c < 4; c++) acc[a][b][c] = 0.f;

    for (int t = 0; t < 25; t++) {
        if (t <= 22)      asm volatile("cp.async.wait_group 2;");
        else if (t == 23) asm volatile("cp.async.wait_group 1;");
        else              asm volatile("cp.async.wait_group 0;");
        __syncthreads();
        if (t + 3 < 25) { stsx(t + 3); issueW(t + 3); }
        if (t + 4 < 25) ldgx(t + 4);

        const uint32_t xs = smb + (uint32_t)((t & 3) * STG);
        const uint32_t ws = xs + XSTG;
#pragma unroll
        for (int ks = 0; ks < 2; ks++) {
            uint32_t A[2][4];
#pragma unroll
            for (int mf = 0; mf < 2; mf++)
                lds128(A[mf], ws + (uint32_t)(((ks * 16 + wm * 2 + mf) * 32 + lane) * 16));
#pragma unroll
            for (int nfp = 0; nfp < 2; nfp++) {
                uint32_t B[4];
                uint32_t badr = xs
                    + (uint32_t)((wn * 32 + nfp * 16 + (lane & 7) + ((lane >> 4) & 1) * 8) * XP
                                 + ks * 32 + ((lane >> 3) & 1) * 16);
                ldm4(B, badr);
#pragma unroll
                for (int mf = 0; mf < 2; mf++) {
                    mma16(acc[mf][nfp * 2],     A[mf], B[0], B[1]);
                    mma16(acc[mf][nfp * 2 + 1], A[mf], B[2], B[3]);
                }
            }
        }
    }
    __syncthreads();   // ring consumed; safe to overwrite with h1

    // epilogue 1: relu(acc+b1) -> h1 fp16 [n1 rows, 144B pitch][64b]
#pragma unroll
    for (int mf = 0; mf < 2; mf++) {
        int n = wm * 32 + mf * 16 + g;
        float bi0 = B1f[n], bi8 = B1f[n + 8];
#pragma unroll
        for (int nf = 0; nf < 4; nf++) {
            int bc = wn * 32 + nf * 8 + 2 * q;
            float* a = acc[mf][nf];
            sts32(smb + (uint32_t)(OFF_H1 + n * HP + bc * 2),
                  h2pk(fmaxf(a[0] + bi0, 0.f), fmaxf(a[1] + bi0, 0.f)));
            sts32(smb + (uint32_t)(OFF_H1 + (n + 8) * HP + bc * 2),
                  h2pk(fmaxf(a[2] + bi8, 0.f), fmaxf(a[3] + bi8, 0.f)));
        }
    }
    __syncthreads();

    // ---------------- GEMM2: [128n2] x [256k] x [64b], A from global --------
    float a2[4][4];
#pragma unroll
    for (int b = 0; b < 4; b++)
#pragma unroll
        for (int c = 0; c < 4; c++) a2[b][c] = 0.f;

    uint4 anx = g_w2h[wm * 32 + lane];
#pragma unroll 4
    for (int ks = 0; ks < 16; ks++) {
        uint32_t A[4];
        A[0] = anx.x; A[1] = anx.y; A[2] = anx.z; A[3] = anx.w;
        if (ks < 15) anx = g_w2h[((ks + 1) * 8 + wm) * 32 + lane];
#pragma unroll
        for (int nfp = 0; nfp < 2; nfp++) {
            uint32_t B[4];
            uint32_t badr = smb
                + (uint32_t)(OFF_H1 + (ks * 16 + (lane & 7) + ((lane >> 3) & 1) * 8) * HP
                             + (wn * 32 + nfp * 16 + ((lane >> 4) & 1) * 8) * 2);
            ldm4t(B, badr);
            mma16(a2[nfp * 2],     A, B[0], B[1]);
            mma16(a2[nfp * 2 + 1], A, B[2], B[3]);
        }
    }

    // epilogue 2: relu(a2+b2) -> h2 fp16 [n2 rows][64b]
    {
        int n = wm * 16 + g;
        float bi0 = B2f[n], bi8 = B2f[n + 8];
#pragma unroll
        for (int nf = 0; nf < 4; nf++) {
            int bc = wn * 32 + nf * 8 + 2 * q;
            float* a = a2[nf];
            sts32(smb + (uint32_t)(OFF_H2 + n * HP + bc * 2),
                  h2pk(fmaxf(a[0] + bi0, 0.f), fmaxf(a[1] + bi0, 0.f)));
            sts32(smb + (uint32_t)(OFF_H2 + (n + 8) * HP + bc * 2),
                  h2pk(fmaxf(a[2] + bi8, 0.f), fmaxf(a[3] + bi8, 0.f)));
        }
    }
    __syncthreads();

    // ---------------- GEMM3: [16n3] x [128k] x [64b], 8 warps x 8b ----------
    if (w < 8) {
        float a3[4] = {0.f, 0.f, 0.f, 0.f};
        uint4 a3nx = g_w3h[lane];
#pragma unroll
        for (int ks = 0; ks < 8; ks++) {
            uint32_t A[4];
            A[0] = a3nx.x; A[1] = a3nx.y; A[2] = a3nx.z; A[3] = a3nx.w;
            if (ks < 7) a3nx = g_w3h[(ks + 1) * 32 + lane];
            uint32_t B[2];
            int l = lane & 15;
            uint32_t badr = smb
                + (uint32_t)(OFF_H2 + (ks * 16 + (l & 7) + ((l >> 3) & 1) * 8) * HP + w * 16);
            ldm2t(B, badr);
            mma16(a3, A, B[0], B[1]);
        }
        int b = m0 + w * 8 + 2 * q;
        out[(size_t)b * 10 + g]       = a3[0] + B3f[g];
        out[(size_t)(b + 1) * 10 + g] = a3[1] + B3f[g];
        if (g < 2) {
            out[(size_t)b * 10 + g + 8]       = a3[2] + B3f[g + 8];
            out[(size_t)(b + 1) * 10 + g + 8] = a3[3] + B3f[g + 8];
        }
    }
}

// ---------------------------------------------------------------------------
extern "C" void kernel_launch(void* const* d_in, const int* in_sizes, int n_in,
                              void* d_out, int out_size) {
    const float* x    = (const float*)d_in[0];
    const float* conv = (const float*)d_in[1];
    const float* w1   = (const float*)d_in[2];
    const float* b1   = (const float*)d_in[3];
    const float* w2   = (const float*)d_in[4];
    const float* b2   = (const float*)d_in[5];
    const float* w3   = (const float*)d_in[6];
    const float* b3   = (const float*)d_in[7];
    float* out = (float*)d_out;

    prep_kernel<<<417, 256>>>(conv, w1, w2, w3);

    cudaFuncSetAttribute(fused_kernel, cudaFuncAttributeMaxDynamicSharedMemorySize, SMEMB);
    fused_kernel<<<1024, 512, SMEMB>>>(x, b1, b2, b3, out);
}